// round 15
// baseline (speedup 1.0000x reference)
#include <cuda_runtime.h>
#include <math.h>
#include <float.h>
#include <stdint.h>

// Problem constants
#define H_   248
#define W_   216
#define HW   (H_*W_)          // 53568
#define NANCH 6
#define NTOT (HW*NANCH)       // 321408 rows per batch
#define NT4  (NTOT/4)         // 80352
#define BSZ  16
#define NPRE 100
#define MAXN 50
#define NBINS 2048
#define CAP   3072

// Scratch (static device globals; zero-initialized at load)
__device__ unsigned g_key[BSZ][NTOT];           // fkey(max logit), layout j = a*HW + s
__device__ int g_hist[BSZ][NBINS];
__device__ int g_thr[BSZ];
__device__ int g_cnt[BSZ];
__device__ unsigned long long g_ck[BSZ][CAP];   // packed (fkey<<32)|(~i), i = s*6+a
__device__ float g_bbx[BSZ][NPRE][7];
__device__ float g_b2dx[BSZ][NPRE][4];
__device__ float g_areax[BSZ][NPRE];
__device__ float g_sc3x[BSZ][3][NPRE];
__device__ float g_fv[BSZ][3*NPRE];

__device__ __forceinline__ unsigned fkey(float v) {
    unsigned b = __float_as_uint(v);
    return (b & 0x80000000u) ? ~b : (b | 0x80000000u); // monotone float->uint
}

// ---------------------------------------------------------------------------
// Pass 1: per-row max logit -> u32 key array + per-batch histogram (11-bit).
// Two float4-groups per thread for MLP; warp-aggregated shared atomics.
#define SGRP 40192   // stride between the two groups (>= NT4/2)
__global__ void k_score(const float* __restrict__ cls) {
    __shared__ int sh[NBINS];
    for (int i = threadIdx.x; i < NBINS; i += blockDim.x) sh[i] = 0;
    __syncthreads();

    int b = blockIdx.y;
    int g0 = blockIdx.x * blockDim.x + threadIdx.x;
    int lane = threadIdx.x & 31;

    #pragma unroll
    for (int g = 0; g < 2; g++) {
        int j4 = g0 + g * SGRP;
        unsigned bins[4] = {0xFFFFFFFFu, 0xFFFFFFFFu, 0xFFFFFFFFu, 0xFFFFFFFFu};
        if (j4 < NT4) {
            int j = j4 * 4;
            int a = j / HW, s = j - a * HW;   // 4-group never crosses 'a' (HW%4==0)
            const float4* base = (const float4*)(cls + (size_t)b * 18 * HW
                                                 + (size_t)(3 * a) * HW + s);
            float4 v0 = base[0];
            float4 v1 = base[HW / 4];
            float4 v2 = base[2 * (HW / 4)];
            uint4 kk;
            kk.x = fkey(fmaxf(v0.x, fmaxf(v1.x, v2.x)));
            kk.y = fkey(fmaxf(v0.y, fmaxf(v1.y, v2.y)));
            kk.z = fkey(fmaxf(v0.z, fmaxf(v1.z, v2.z)));
            kk.w = fkey(fmaxf(v0.w, fmaxf(v1.w, v2.w)));
            ((uint4*)g_key[b])[j4] = kk;
            bins[0] = kk.x >> 21; bins[1] = kk.y >> 21;
            bins[2] = kk.z >> 21; bins[3] = kk.w >> 21;
        }
        #pragma unroll
        for (int k = 0; k < 4; k++) {
            unsigned bk = bins[k];
            unsigned mask = __match_any_sync(0xFFFFFFFFu, bk);
            if (bk != 0xFFFFFFFFu && lane == (__ffs(mask) - 1))
                atomicAdd(&sh[bk], __popc(mask));
        }
    }
    __syncthreads();
    for (int i = threadIdx.x; i < NBINS; i += blockDim.x)
        if (sh[i]) atomicAdd(&g_hist[b][i], sh[i]);
}

// Threshold bin per batch: largest t with sum_{k>=t} hist[k] >= NPRE.
// Also zeroes the histogram for the next graph replay.
__global__ void k_thresh() {
    int b = blockIdx.x, tid = threadIdx.x;  // 256 threads
    __shared__ int a[256];
    __shared__ int red[256];
    int binv[8];
    int base = tid * 8, s = 0;
    #pragma unroll
    for (int k = 0; k < 8; k++) { binv[k] = g_hist[b][base + k]; s += binv[k]; }
    a[tid] = s;
    __syncthreads();
    #pragma unroll
    for (int k = 0; k < 8; k++) g_hist[b][base + k] = 0;   // reset for replay
    // inclusive suffix sum over 256 chunk sums
    for (int off = 1; off < 256; off <<= 1) {
        int t = (tid + off < 256) ? a[tid + off] : 0;
        __syncthreads();
        a[tid] += t;
        __syncthreads();
    }
    int acc = (tid < 255) ? a[tid + 1] : 0;   // sum of chunks strictly above mine
    int best = 0;
    for (int k = 7; k >= 0; k--) {
        acc += binv[k];
        if (acc >= NPRE) { best = base + k; break; }
    }
    red[tid] = best;
    __syncthreads();
    for (int off = 128; off > 0; off >>= 1) {
        if (tid < off) red[tid] = max(red[tid], red[tid + off]);
        __syncthreads();
    }
    if (tid == 0) g_thr[b] = red[0];
}

// Collect candidates above threshold from L2-resident key array; emit full
// packed u64 ordering keys so downstream needs no re-gather.
__global__ void k_collect() {
    int b = blockIdx.y;
    unsigned t = (unsigned)g_thr[b];
    int j4 = blockIdx.x * blockDim.x + threadIdx.x;
    if (j4 >= NT4) return;
    uint4 kk = ((const uint4*)g_key[b])[j4];
    unsigned kv[4] = {kk.x, kk.y, kk.z, kk.w};
    int j = j4 * 4;
    #pragma unroll
    for (int k = 0; k < 4; k++) {
        if ((kv[k] >> 21) >= t) {
            int slot = atomicAdd(&g_cnt[b], 1);
            if (slot < CAP) {
                int jk = j + k;
                int a2 = jk / HW, s2 = jk - a2 * HW;
                unsigned i = (unsigned)(s2 * 6 + a2);   // original reshaped row
                g_ck[b][slot] = ((unsigned long long)kv[k] << 32) | (0xFFFFFFFFu - i);
            }
        }
    }
}

// Rank-sort candidates O(C^2) (exact lax.top_k order), decode top-100 boxes.
__global__ void k_rankdecode(const float* __restrict__ cls,
                             const float* __restrict__ box,
                             const float* __restrict__ dir,
                             const float* __restrict__ anc) {
    int b = blockIdx.x, tid = threadIdx.x;  // 256 threads
    __shared__ unsigned long long ck[CAP];
    __shared__ int topi[NPRE];
    __shared__ int sC;
    if (tid == 0) {
        sC = min(g_cnt[b], CAP);
        g_cnt[b] = 0;   // reset for next graph replay (race-free: published below)
    }
    __syncthreads();
    int C = sC;
    for (int u = tid; u < C; u += 256) ck[u] = g_ck[b][u];
    __syncthreads();
    for (int u = tid; u < C; u += 256) {
        unsigned long long k = ck[u];
        int r = 0;
        for (int w = 0; w < C; w++) r += (ck[w] > k);
        if (r < NPRE) topi[r] = (int)(0xFFFFFFFFu - (unsigned)k);
    }
    __syncthreads();

    if (tid < NPRE) {
        const float PI = 3.14159265358979323846f;
        int i = topi[tid];
        int s = i / 6, a = i - 6 * s;

        const float* cb = cls + (size_t)b * 18 * HW + s;
        #pragma unroll
        for (int c = 0; c < 3; c++) {
            float x = cb[(size_t)(3 * a + c) * HW];
            g_sc3x[b][c][tid] = 0.5f * tanhf(0.5f * x) + 0.5f; // sigmoid
        }

        const float* pb = box + (size_t)b * 42 * HW + s;
        float d[7];
        #pragma unroll
        for (int j = 0; j < 7; j++) d[j] = pb[(size_t)(7 * a + j) * HW];

        const float* db = dir + (size_t)b * 12 * HW + s;
        float d0 = db[(size_t)(2 * a) * HW];
        float d1 = db[(size_t)(2 * a + 1) * HW];
        int dircls = (d1 > d0) ? 1 : 0;

        const float* ab = anc + (size_t)i * 7;
        float xa = ab[0], ya = ab[1], za = ab[2];
        float wa = ab[3], la = ab[4], ha = ab[5], ra = ab[6];

        float da = sqrtf(wa * wa + la * la);
        float x = d[0] * da + xa;
        float y = d[1] * da + ya;
        float z = d[2] * ha + za + ha * 0.5f;
        float w = wa * expf(d[3]);
        float l = la * expf(d[4]);
        float h = ha * expf(d[5]);
        z = z - h * 0.5f;
        float th0 = ra + d[6];
        float lp  = th0 - floorf(th0 / PI + 1.0f) * PI;
        float th  = lp + (1.0f - (float)dircls) * PI;

        g_bbx[b][tid][0] = x; g_bbx[b][tid][1] = y; g_bbx[b][tid][2] = z;
        g_bbx[b][tid][3] = w; g_bbx[b][tid][4] = l; g_bbx[b][tid][5] = h;
        g_bbx[b][tid][6] = th;

        float x1 = x - w * 0.5f, y1 = y - l * 0.5f;
        float x2 = x + w * 0.5f, y2 = y + l * 0.5f;
        g_b2dx[b][tid][0] = x1; g_b2dx[b][tid][1] = y1;
        g_b2dx[b][tid][2] = x2; g_b2dx[b][tid][3] = y2;
        g_areax[b][tid] = (x2 - x1) * (y2 - y1);
    }
}

// Per (batch, class): sort, parallel suppression bit-matrix, bitwise greedy sweep
__global__ void k_nms() {
    int c = blockIdx.x, b = blockIdx.y, tid = threadIdx.x;  // 128 threads

    __shared__ unsigned long long key[NPRE];
    __shared__ float kvs[NPRE];
    __shared__ int   ord[NPRE];
    __shared__ float sx1[NPRE], sy1[NPRE], sx2[NPRE], sy2[NPRE], sar[NPRE];
    __shared__ unsigned supw[NPRE][4];
    __shared__ unsigned km[4];

    if (tid < 4) km[tid] = 0;
    if (tid < NPRE) {
        float s = g_sc3x[b][c][tid];
        float kv = (s > 0.1f) ? s : -FLT_MAX;   // valid ? score : -inf key
        kvs[tid] = kv;
        key[tid] = ((unsigned long long)fkey(kv) << 32) | (0xFFFFFFFFu - (unsigned)tid);
    }
    __syncthreads();
    if (tid < NPRE) {   // stable descending rank (exact argsort semantics)
        unsigned long long k = key[tid];
        int r = 0;
        #pragma unroll 4
        for (int u = 0; u < NPRE; u++) r += (key[u] > k);
        ord[r] = tid;
    }
    __syncthreads();
    if (tid < NPRE) {   // gather boxes in sorted order, init keep bits = valid
        int p = ord[tid];
        sx1[tid] = g_b2dx[b][p][0]; sy1[tid] = g_b2dx[b][p][1];
        sx2[tid] = g_b2dx[b][p][2]; sy2[tid] = g_b2dx[b][p][3];
        sar[tid] = g_areax[b][p];
        if (kvs[p] != -FLT_MAX) atomicOr(&km[tid >> 5], 1u << (tid & 31));
    }
    __syncthreads();
    if (tid < NPRE) {   // suppression row ii=tid vs all jj>ii, in parallel
        float ax1 = sx1[tid], ay1 = sy1[tid], ax2 = sx2[tid], ay2 = sy2[tid];
        float aa = sar[tid];
        unsigned w0 = 0, w1 = 0, w2 = 0, w3 = 0;
        for (int jj = tid + 1; jj < NPRE; jj++) {
            float x1 = fmaxf(ax1, sx1[jj]);
            float y1 = fmaxf(ay1, sy1[jj]);
            float x2 = fminf(ax2, sx2[jj]);
            float y2 = fminf(ay2, sy2[jj]);
            float inter = fmaxf(x2 - x1, 0.0f) * fmaxf(y2 - y1, 0.0f);
            float iou = inter / (aa + sar[jj] - inter + 1e-8f);
            if (iou > 0.01f) {
                unsigned bit = 1u << (jj & 31);
                if (jj < 32) w0 |= bit; else if (jj < 64) w1 |= bit;
                else if (jj < 96) w2 |= bit; else w3 |= bit;
            }
        }
        supw[tid][0] = w0; supw[tid][1] = w1; supw[tid][2] = w2; supw[tid][3] = w3;
    }
    __syncthreads();
    if (tid == 0) {     // greedy sweep: 128-bit register AND-NOT, 100 iterations
        unsigned k0 = km[0], k1 = km[1], k2 = km[2], k3 = km[3];
        for (int ii = 0; ii < NPRE; ii++) {
            unsigned bit;
            if (ii < 32) bit = (k0 >> ii) & 1u;
            else if (ii < 64) bit = (k1 >> (ii - 32)) & 1u;
            else if (ii < 96) bit = (k2 >> (ii - 64)) & 1u;
            else bit = (k3 >> (ii - 96)) & 1u;
            if (bit) {
                k0 &= ~supw[ii][0]; k1 &= ~supw[ii][1];
                k2 &= ~supw[ii][2]; k3 &= ~supw[ii][3];
            }
        }
        km[0] = k0; km[1] = k1; km[2] = k2; km[3] = k3;
    }
    __syncthreads();
    if (tid < NPRE) {   // fv[p] = keep ? score : -1  (keep already includes valid)
        int p = ord[tid];
        unsigned bit = (km[tid >> 5] >> (tid & 31)) & 1u;
        g_fv[b][c * NPRE + p] = bit ? g_sc3x[b][c][p] : -1.0f;
    }
}

// Final top-50 over 300 flat entries, (value desc, flat index asc) — exact top_k
__global__ void k_out(float* __restrict__ out) {
    int b = blockIdx.x, tid = threadIdx.x;  // 320 threads, 300 active
    __shared__ unsigned long long key[3 * NPRE];
    __shared__ float fvs[3 * NPRE];
    if (tid < 3 * NPRE) {
        float v = g_fv[b][tid];
        fvs[tid] = v;
        key[tid] = ((unsigned long long)fkey(v) << 32) | (0xFFFFFFFFu - (unsigned)tid);
    }
    __syncthreads();
    if (tid < 3 * NPRE) {
        unsigned long long k = key[tid];
        int r = 0;
        #pragma unroll 4
        for (int u = 0; u < 3 * NPRE; u++) r += (key[u] > k);
        if (r < MAXN) {
            int sel = tid % NPRE;
            int lab = tid / NPRE;
            float v = fvs[tid];
            float* ob = out + (size_t)b * MAXN * 7 + (size_t)r * 7;
            #pragma unroll
            for (int j = 0; j < 7; j++) ob[j] = g_bbx[b][sel][j];
            out[BSZ * MAXN * 7 +                  b * MAXN + r] = (float)lab;
            out[BSZ * MAXN * 7 + BSZ * MAXN +     b * MAXN + r] = v;
            out[BSZ * MAXN * 7 + 2 * BSZ * MAXN + b * MAXN + r] = (v > 0.0f) ? 1.0f : 0.0f;
        }
    }
}

// ---------------------------------------------------------------------------
extern "C" void kernel_launch(void* const* d_in, const int* in_sizes, int n_in,
                              void* d_out, int out_size) {
    const float* cls = (const float*)d_in[0]; // (16,18,248,216)
    const float* box = (const float*)d_in[1]; // (16,42,248,216)
    const float* dir = (const float*)d_in[2]; // (16,12,248,216)
    const float* anc = (const float*)d_in[3]; // (248,216,3,2,7)
    float* out = (float*)d_out;

    dim3 gS((SGRP + 255) / 256, BSZ);          // 2 groups/thread
    k_score<<<gS, 256>>>(cls);

    k_thresh<<<BSZ, 256>>>();

    dim3 gC((NT4 + 255) / 256, BSZ);
    k_collect<<<gC, 256>>>();

    k_rankdecode<<<BSZ, 256>>>(cls, box, dir, anc);

    dim3 gN(3, BSZ);
    k_nms<<<gN, 128>>>();

    k_out<<<BSZ, 320>>>(out);
}